// round 15
// baseline (speedup 1.0000x reference)
#include <cuda_runtime.h>
#include <cuda_fp16.h>
#include <math.h>
#include <stdint.h>

// Problem constants
#define Bv   32
#define Sv   512
#define Dv   768
#define Mv   32
#define Tv   30
#define Hv   12
#define HDv  64
#define DFFv 3072
#define Lv   4
#define Ev   100000
#define NT   1024           // B*M token rows

// ---------------- scratch (static device memory; no allocations) -------------
__device__ float  g_x[NT * Dv];            // residual stream (exact fp32)
__device__ __half g_xh[NT * Dv];           // fp16 copy of residual (GEMM A)
__device__ __half g_qkvh[NT * 3 * Dv];     // fp16 QKV (bias fused)
__device__ __half g_buf1h[NT * DFFv];      // attn-out / FF hidden (fp16)
__device__ __half g_hidh[NT * 128];        // classifier hidden, K padded to 128
__device__ float  g_part[2 * NT * DFFv];   // split-K partials (fp32)

// ---- fp16 weight arena: offsets DERIVED from model constants ---------------
#define N_IPW (Lv * 3 * Dv * Dv)
#define N_OW  (Lv * Dv * Dv)
#define N_L1W (Lv * DFFv * Dv)
#define N_L2W (Lv * Dv * DFFv)
#define N_C1W (100 * Dv)
#define N_C2W (Ev * 128)

#define OFF_IPW 0u
#define OFF_OW  ((unsigned)(OFF_IPW + N_IPW))
#define OFF_L1W ((unsigned)(OFF_OW + N_OW))
#define OFF_L2W ((unsigned)(OFF_L1W + N_L1W))
#define OFF_C1W ((unsigned)(OFF_L2W + N_L2W))
#define OFF_C2W ((unsigned)(OFF_C1W + N_C1W))
#define WH_TOTAL ((unsigned)(OFF_C2W + N_C2W))
__device__ __half g_wh[WH_TOTAL];

// chunk (8-elem) boundaries for fused cvt — derived
#define CH_IPW (N_IPW / 8)
#define CH_OW  (CH_IPW + N_OW / 8)
#define CH_L1  (CH_OW + N_L1W / 8)
#define CH_L2  (CH_L1 + N_L2W / 8)
#define CH_C1  (CH_L2 + N_C1W / 8)

// ======================= helpers ============================================
__device__ __forceinline__ void mma_f16(float* c, uint32_t a0, uint32_t a1,
                                        uint32_t a2, uint32_t a3,
                                        uint32_t b0, uint32_t b1) {
    asm volatile(
        "mma.sync.aligned.m16n8k16.row.col.f32.f16.f16.f32 "
        "{%0,%1,%2,%3}, {%4,%5,%6,%7}, {%8,%9}, {%0,%1,%2,%3};"
        : "+f"(c[0]), "+f"(c[1]), "+f"(c[2]), "+f"(c[3])
        : "r"(a0), "r"(a1), "r"(a2), "r"(a3), "r"(b0), "r"(b1));
}

__device__ __forceinline__ void cp16(unsigned dst, const void* src, int bytes) {
    asm volatile("cp.async.ca.shared.global [%0], [%1], 16, %2;\n"
                 :: "r"(dst), "l"(src), "r"(bytes));
}

// ======================= fused weight conversion =============================
__global__ void __launch_bounds__(256) cvt_all_kernel(
    const float* __restrict__ ipw, const float* __restrict__ ow,
    const float* __restrict__ l1w, const float* __restrict__ l2w,
    const float* __restrict__ c1w, __half* __restrict__ wh)
{
    int stride = gridDim.x * blockDim.x;
    for (int i = blockIdx.x * blockDim.x + threadIdx.x; i < CH_C1; i += stride) {
        const float* src;
        __half* dst;
        if (i < CH_IPW)      { src = ipw + (size_t)i * 8;
                               dst = wh + OFF_IPW + (size_t)i * 8; }
        else if (i < CH_OW)  { size_t j = i - CH_IPW; src = ow + j * 8;
                               dst = wh + OFF_OW + j * 8; }
        else if (i < CH_L1)  { size_t j = i - CH_OW;  src = l1w + j * 8;
                               dst = wh + OFF_L1W + j * 8; }
        else if (i < CH_L2)  { size_t j = i - CH_L1;  src = l2w + j * 8;
                               dst = wh + OFF_L2W + j * 8; }
        else                 { size_t j = i - CH_L2;  src = c1w + j * 8;
                               dst = wh + OFF_C1W + j * 8; }
        float4 f0 = *(const float4*)src;
        float4 f1 = *(const float4*)(src + 4);
        __half2 h[4];
        h[0] = __floats2half2_rn(f0.x, f0.y);
        h[1] = __floats2half2_rn(f0.z, f0.w);
        h[2] = __floats2half2_rn(f1.x, f1.y);
        h[3] = __floats2half2_rn(f1.z, f1.w);
        *(uint4*)dst = *(uint4*)h;
    }
}

// cls2 weights [100000,100] -> padded [100000,128] fp16
__global__ void __launch_bounds__(256) cvt_pad_kernel(
    const float* __restrict__ src, __half* __restrict__ dst)
{
    int stride = gridDim.x * blockDim.x;
    const int total = Ev * 32;
    for (int t = blockIdx.x * blockDim.x + threadIdx.x; t < total; t += stride) {
        int r = t >> 5, c4 = (t & 31) * 4;
        __half2 lo, hi;
        if (c4 < 100) {
            float4 f = *(const float4*)(src + (size_t)r * 100 + c4);
            lo = __floats2half2_rn(f.x, f.y);
            hi = __floats2half2_rn(f.z, f.w);
        } else {
            lo = __floats2half2_rn(0.f, 0.f);
            hi = lo;
        }
        __half2 p[2] = { lo, hi };
        *(uint2*)(dst + (size_t)r * 128 + c4) = *(uint2*)p;
    }
}

// ======================= fp16 tensor-core GEMM (templated M-tile) ===========
// MROWS in {128, 64}. 256 threads, 8 warps (2x4), warp tile (MROWS/2)x32.
// mode: bit0 = relu, bit1 = fp16 output, bit2 = streaming stores.
#define HSTRD 48

template<int MROWS>
__device__ __forceinline__ void fill_tiles_h(
    __half* As, __half* Ws, const __half* __restrict__ A,
    const __half* __restrict__ W,
    int rowBase, int colBase, int N, int K, int k0, int kEnd, int tid)
{
    #pragma unroll
    for (int i = 0; i < MROWS / 64; i++) {
        int c = tid + i * 256;
        int r = c >> 2, ck = c & 3;
        int gk = k0 + ck * 8;
        int ok = (gk < kEnd);
        const __half* src = ok ? (A + (size_t)(rowBase + r) * K + gk) : A;
        unsigned d = (unsigned)__cvta_generic_to_shared(As + r * HSTRD + ck * 8);
        cp16(d, src, ok ? 16 : 0);
    }
    #pragma unroll
    for (int i = 0; i < 2; i++) {
        int c = tid + i * 256;
        int r = c >> 2, ck = c & 3;
        int gk = k0 + ck * 8;
        int n = colBase + r;
        int ok = (n < N) && (gk < kEnd);
        const __half* src = ok ? (W + (size_t)n * K + gk) : W;
        unsigned d = (unsigned)__cvta_generic_to_shared(Ws + r * HSTRD + ck * 8);
        cp16(d, src, ok ? 16 : 0);
    }
}

template<int MROWS>
__global__ void __launch_bounds__(256, 2) gemm_h(
    const __half* __restrict__ A, const __half* __restrict__ W,
    const float* __restrict__ bias, void* Cv,
    int N, int K, int kChunk, int mode)
{
    constexpr int ASMS = MROWS * HSTRD;       // A stage halfs
    constexpr int WSMS = 128 * HSTRD;         // W stage halfs
    constexpr int MT = MROWS / 32;            // warp m-subtiles

    extern __shared__ __half hs[];
    __half* AsBase = hs;                      // [2][MROWS][HSTRD]
    __half* WsBase = hs + 2 * ASMS;           // [2][128][HSTRD]

    const int tid = threadIdx.x;
    const int lane = tid & 31, wid = tid >> 5;
    const int wy = wid >> 2, wx = wid & 3;
    const int lm = lane >> 2, lk = lane & 3;
    const int rowBase = blockIdx.y * MROWS;
    const int colBase = blockIdx.x * 128;
    const int kBase = blockIdx.z * kChunk;
    const int kEnd = min(K, kBase + kChunk);
    const int nT = (kEnd - kBase + 31) >> 5;

    float acc[MT][4][4];
    #pragma unroll
    for (int i = 0; i < MT; i++)
        #pragma unroll
        for (int j = 0; j < 4; j++)
            #pragma unroll
            for (int q = 0; q < 4; q++) acc[i][j][q] = 0.f;

    fill_tiles_h<MROWS>(AsBase, WsBase, A, W, rowBase, colBase, N, K, kBase, kEnd, tid);
    asm volatile("cp.async.commit_group;\n" ::: "memory");

    for (int t = 0; t < nT; t++) {
        const int cur = t & 1;
        if (t + 1 < nT)
            fill_tiles_h<MROWS>(AsBase + (cur ^ 1) * ASMS, WsBase + (cur ^ 1) * WSMS,
                                A, W, rowBase, colBase, N, K, kBase + (t + 1) * 32, kEnd, tid);
        asm volatile("cp.async.commit_group;\n" ::: "memory");
        asm volatile("cp.async.wait_group 1;\n" ::: "memory");
        __syncthreads();

        const __half* as = AsBase + cur * ASMS;
        const __half* ws = WsBase + cur * WSMS;
        #pragma unroll
        for (int ks = 0; ks < 2; ks++) {
            const int kb = ks * 16;
            uint2 afr[MT][2];
            #pragma unroll
            for (int mt = 0; mt < MT; mt++) {
                int m = wy * (MROWS / 2) + mt * 16 + lm;
                afr[mt][0] = *(const uint2*)(as + m * HSTRD + kb + 4 * lk);
                afr[mt][1] = *(const uint2*)(as + (m + 8) * HSTRD + kb + 4 * lk);
            }
            uint2 bfr[4];
            #pragma unroll
            for (int nt = 0; nt < 4; nt++) {
                int n = wx * 32 + nt * 8 + lm;
                bfr[nt] = *(const uint2*)(ws + n * HSTRD + kb + 4 * lk);
            }
            #pragma unroll
            for (int mt = 0; mt < MT; mt++)
                #pragma unroll
                for (int nt = 0; nt < 4; nt++)
                    mma_f16(acc[mt][nt],
                            afr[mt][0].x, afr[mt][1].x,
                            afr[mt][0].y, afr[mt][1].y,
                            bfr[nt].x, bfr[nt].y);
        }
        __syncthreads();
    }

    // ======== smem-staged epilogue ========
    const int relu = mode & 1, halfOut = mode & 2, streamC = mode & 4;

    if (!halfOut) {
        float* Cf = (float*)Cv;
        if (gridDim.z > 1) Cf += (size_t)blockIdx.z * ((size_t)NT * N);
        float* sf = (float*)hs;              // 64 x 132 floats
        #pragma unroll
        for (int ph = 0; ph < MROWS / 64; ph++) {
            if (MROWS == 64 || wy == ph) {
                #pragma unroll
                for (int mt = 0; mt < MT; mt++) {
                    #pragma unroll
                    for (int nt = 0; nt < 4; nt++) {
                        int lr = (MROWS == 64 ? wy * 32 : 0) + mt * 16 + lm;
                        int c0 = wx * 32 + nt * 8 + lk * 2;
                        int gc = colBase + c0;
                        float bx = 0.f, by = 0.f;
                        if (bias) {
                            if (gc < N)     bx = bias[gc];
                            if (gc + 1 < N) by = bias[gc + 1];
                        }
                        float v00 = acc[mt][nt][0] + bx, v01 = acc[mt][nt][1] + by;
                        float v10 = acc[mt][nt][2] + bx, v11 = acc[mt][nt][3] + by;
                        if (relu) {
                            v00 = fmaxf(v00, 0.f); v01 = fmaxf(v01, 0.f);
                            v10 = fmaxf(v10, 0.f); v11 = fmaxf(v11, 0.f);
                        }
                        *(float2*)(sf + lr * 132 + c0)       = make_float2(v00, v01);
                        *(float2*)(sf + (lr + 8) * 132 + c0) = make_float2(v10, v11);
                    }
                }
            }
            __syncthreads();
            int gRowBase = rowBase + ph * 64;
            #pragma unroll
            for (int it = 0; it < 8; it++) {
                int fidx = tid + it * 256;
                int row  = fidx >> 5;
                int col4 = (fidx & 31) << 2;
                float4 v = *(const float4*)(sf + row * 132 + col4);
                int gc = colBase + col4;
                float* dst = Cf + (size_t)(gRowBase + row) * N + gc;
                if (gc + 3 < N) {
                    if (streamC) __stcs((float4*)dst, v);
                    else         *(float4*)dst = v;
                } else {
                    if (gc < N)     dst[0] = v.x;
                    if (gc + 1 < N) dst[1] = v.y;
                    if (gc + 2 < N) dst[2] = v.z;
                }
            }
            __syncthreads();
        }
    } else {
        __half* Ch = (__half*)Cv;
        __half* sh2 = hs;                    // MROWS x 136 halfs
        #pragma unroll
        for (int mt = 0; mt < MT; mt++) {
            #pragma unroll
            for (int nt = 0; nt < 4; nt++) {
                int lr = wy * (MROWS / 2) + mt * 16 + lm;
                int c0 = wx * 32 + nt * 8 + lk * 2;
                int gc = colBase + c0;
                float bx = 0.f, by = 0.f;
                if (bias) {
                    if (gc < N)     bx = bias[gc];
                    if (gc + 1 < N) by = bias[gc + 1];
                }
                float v00 = acc[mt][nt][0] + bx, v01 = acc[mt][nt][1] + by;
                float v10 = acc[mt][nt][2] + bx, v11 = acc[mt][nt][3] + by;
                if (relu) {
                    v00 = fmaxf(v00, 0.f); v01 = fmaxf(v01, 0.f);
                    v10 = fmaxf(v10, 0.f); v11 = fmaxf(v11, 0.f);
                }
                *(__half2*)(sh2 + lr * 136 + c0)       = __floats2half2_rn(v00, v01);
                *(__half2*)(sh2 + (lr + 8) * 136 + c0) = __floats2half2_rn(v10, v11);
            }
        }
        __syncthreads();
        #pragma unroll
        for (int it = 0; it < MROWS / 16; it++) {
            int fidx = tid + it * 256;
            int row  = fidx >> 4;
            int col8 = (fidx & 15) << 3;
            uint4 v = *(const uint4*)(sh2 + row * 136 + col8);
            int gc = colBase + col8;
            __half* dst = Ch + (size_t)(rowBase + row) * N + gc;
            if (gc + 7 < N) {
                *(uint4*)dst = v;
            } else {
                const __half* sv = sh2 + row * 136 + col8;
                for (int j = 0; j < 8; j++)
                    if (gc + j < N) dst[j] = sv[j];
            }
        }
    }
}

#define SMEM_128 (2 * (128 * HSTRD + 128 * HSTRD) * 2)   // 49152 B
#define SMEM_64  (2 * (64 * HSTRD + 128 * HSTRD) * 2)    // 36864 B

// ======================= mention pooling ====================================
__global__ void __launch_bounds__(128) pool_kernel(
    const float* __restrict__ lhs, const float* __restrict__ attn_w,
    const float* __restrict__ attn_b_p, const int* __restrict__ pos,
    const int* __restrict__ emask, float* __restrict__ x, __half* __restrict__ xh)
{
    int bm = blockIdx.x;
    int b = bm / Mv;
    __shared__ float logit[Tv];
    __shared__ float score[Tv];
    __shared__ int   validv[Tv];

    int tid = threadIdx.x, lane = tid & 31, warp = tid >> 5;

    if (tid == 0) {
        int ok = (emask[bm] != 0);
        int alive = 1;
        for (int t = 0; t < Tv; t++) {
            if (pos[bm * Tv + t] == -1) alive = 0;
            validv[t] = ok & alive;
        }
    }
    __syncthreads();

    float ab = attn_b_p[0];
    const float* lb = lhs + (size_t)b * Sv * Dv;

    for (int t = warp; t < Tv; t += 4) {
        float s = 0.f;
        for (int d = lane; d < Dv; d += 32) s += lb[t * Dv + d] * attn_w[d];
        for (int o = 16; o; o >>= 1) s += __shfl_xor_sync(0xffffffffu, s, o);
        if (lane == 0) logit[t] = (validv[t] ? s : 0.f) + ab;
    }
    __syncthreads();

    if (tid < 32) {
        float v = (tid < Tv) ? logit[tid] : -INFINITY;
        float mx = v;
        for (int o = 16; o; o >>= 1) mx = fmaxf(mx, __shfl_xor_sync(0xffffffffu, mx, o));
        float e = (tid < Tv) ? expf(v - mx) : 0.f;
        float sm = e;
        for (int o = 16; o; o >>= 1) sm += __shfl_xor_sync(0xffffffffu, sm, o);
        if (tid < Tv) score[tid] = e / sm;
    }
    __syncthreads();

    for (int d = tid; d < Dv; d += 128) {
        float s = 0.f;
        #pragma unroll
        for (int t = 0; t < Tv; t++)
            if (validv[t]) s += score[t] * lb[t * Dv + d];
        x[(size_t)bm * Dv + d]  = s;
        xh[(size_t)bm * Dv + d] = __float2half_rn(s);
    }
}

// ======= attention: reads fp16 qkv (bias already fused) =====================
__global__ void __launch_bounds__(128) attn_kernel(
    const __half* __restrict__ qkv, __half* __restrict__ o)
{
    const int bh = blockIdx.x >> 1;
    const int half_ = blockIdx.x & 1;
    const int b = bh / Hv, h = bh % Hv;
    const int r0 = half_ * 16;

    __shared__ float q[16][68];
    __shared__ float kk[32][68];
    __shared__ float vv[32][68];
    __shared__ float a[16][33];

    const int tid = threadIdx.x;
    const __half* base = qkv + (size_t)(b * Mv) * (3 * Dv) + h * HDv;

    #pragma unroll
    for (int rep = 0; rep < 4; rep++) {
        int idx = tid + rep * 128;
        int i = idx >> 5, d2 = idx & 31;
        __half2 v = *(const __half2*)(base + (size_t)(r0 + i) * (3 * Dv) + d2 * 2);
        float2 f = __half22float2(v);
        q[i][d2 * 2]     = f.x;
        q[i][d2 * 2 + 1] = f.y;
    }
    #pragma unroll
    for (int rep = 0; rep < 8; rep++) {
        int idx = tid + rep * 128;
        int i = idx >> 5, d2 = idx & 31;
        size_t off = (size_t)i * (3 * Dv) + d2 * 2;
        float2 fk = __half22float2(*(const __half2*)(base + off + Dv));
        float2 fv = __half22float2(*(const __half2*)(base + off + 2 * Dv));
        kk[i][d2 * 2]     = fk.x;
        kk[i][d2 * 2 + 1] = fk.y;
        vv[i][d2 * 2]     = fv.x;
        vv[i][d2 * 2 + 1] = fv.y;
    }
    __syncthreads();

    #pragma unroll
    for (int rep = 0; rep < 4; rep++) {
        int idx = tid + rep * 128;
        int i = idx >> 5, j = idx & 31;
        float s = 0.f;
        #pragma unroll
        for (int d = 0; d < 64; d += 4) {
            float4 qa = *(const float4*)&q[i][d];
            float4 ka = *(const float4*)&kk[j][d];
            s += qa.x * ka.x + qa.y * ka.y + qa.z * ka.z + qa.w * ka.w;
        }
        a[i][j] = s * 0.125f;
    }
    __syncthreads();

    int warp = tid >> 5, lane = tid & 31;
    #pragma unroll
    for (int r = 0; r < 4; r++) {
        int i = warp * 4 + r;
        float v = a[i][lane];
        float mx = v;
        for (int off = 16; off; off >>= 1) mx = fmaxf(mx, __shfl_xor_sync(0xffffffffu, mx, off));
        float e = expf(v - mx);
        float sm = e;
        for (int off = 16; off; off >>= 1) sm += __shfl_xor_sync(0xffffffffu, sm, off);
        a[i][lane] = e / sm;
    }
    __syncthreads();

    __half* obase = o + (size_t)(b * Mv + r0) * Dv + h * HDv;
    #pragma unroll
    for (int rep = 0; rep < 8; rep++) {
        int idx = tid + rep * 128;
        int i = idx >> 6, d = idx & 63;
        float s = 0.f;
        #pragma unroll
        for (int j = 0; j < 32; j++) s += a[i][j] * vv[j][d];
        obase[(size_t)i * Dv + d] = __float2half_rn(s);
    }
}

// ===== reduce cls1 split-K partials -> padded fp16 hid [1024][128] ==========
__global__ void __launch_bounds__(256) reduce_hid_kernel(
    __half* __restrict__ dst, const float* __restrict__ part, int nPart)
{
    const size_t total = (size_t)NT * 100;
    const size_t stride = (size_t)gridDim.x * blockDim.x;
    for (size_t idx = (size_t)blockIdx.x * blockDim.x + threadIdx.x;
         idx < total; idx += stride) {
        float s = 0.f;
        for (int p = 0; p < nPart; p++) s += part[(size_t)p * total + idx];
        size_t row = idx / 100, col = idx % 100;
        dst[row * 128 + col] = __float2half_rn(s);
    }
}

// ===== reduce split-K partials + bias + residual add + LayerNorm ============
__global__ void __launch_bounds__(256) reduce_addln_kernel(
    float* __restrict__ x, __half* __restrict__ xh,
    const float* __restrict__ part, int nPart,
    const float* __restrict__ bias,
    const float* __restrict__ w, const float* __restrict__ b)
{
    __shared__ float sh[8];
    __shared__ float s_mean, s_inv;
    const int row = blockIdx.x;
    float* xr = x + (size_t)row * Dv;
    __half* xt = xh + (size_t)row * Dv;
    const int tid = threadIdx.x, lane = tid & 31, warp = tid >> 5;
    const size_t planeStride = (size_t)NT * Dv;

    float v[3];
    float sum = 0.f;
    #pragma unroll
    for (int i = 0; i < 3; i++) {
        int idx = tid + 256 * i;
        float d = bias[idx];
        for (int p = 0; p < nPart; p++)
            d += part[(size_t)p * planeStride + (size_t)row * Dv + idx];
        v[i] = xr[idx] + d;
        sum += v[i];
    }
    for (int o = 16; o; o >>= 1) sum += __shfl_xor_sync(0xffffffffu, sum, o);
    if (lane == 0) sh[warp] = sum;
    __syncthreads();
    if (tid == 0) {
        float s = 0.f;
        for (int i = 0; i < 8; i++) s += sh[i];
        s_mean = s * (1.f / (float)Dv);
    }
    __syncthreads();
    float mean = s_mean;

    float sq = 0.f;
    #pragma unroll
    for (int i = 0; i < 3; i++) { float c = v[i] - mean; sq += c * c; }
    for (int o = 16; o; o >>= 1) sq += __shfl_xor_sync(0xffffffffu, sq, o);
    if (lane == 0) sh[warp] = sq;
    __syncthreads();
    if (tid == 0) {
        float s = 0.f;
        for (int i = 0; i < 8; i++) s += sh[i];
        s_inv = rsqrtf(s * (1.f / (float)Dv) + 1e-5f);
    }
    __syncthreads();
    float inv = s_inv;

    #pragma unroll
    for (int i = 0; i < 3; i++) {
        int idx = tid + 256 * i;
        float o = (v[i] - mean) * inv * w[idx] + b[idx];
        xr[idx] = o;
        xt[idx] = __float2half_rn(o);
    }
}

// ======================= launcher ===========================================
extern "C" void kernel_launch(void* const* d_in, const int* in_sizes, int n_in,
                              void* d_out, int out_size)
{
    const float* lhs       = (const float*)d_in[0];
    const float* attn_w    = (const float*)d_in[1];
    const float* attn_b    = (const float*)d_in[2];
    const float* in_proj_w = (const float*)d_in[3];
    const float* in_proj_b = (const float*)d_in[4];
    const float* out_w     = (const float*)d_in[5];
    const float* out_b     = (const float*)d_in[6];
    const float* ln1_w     = (const float*)d_in[7];
    const float* ln1_b     = (const float*)d_in[8];
    const float* lin1_w    = (const float*)d_in[9];
    const float* lin1_b    = (const float*)d_in[10];
    const float* lin2_w    = (const float*)d_in[11];
    const float* lin2_b    = (const float*)d_in[12];
    const float* ln2_w     = (const float*)d_in[13];
    const float* ln2_b     = (const float*)d_in[14];
    const float* cls_w1    = (const float*)d_in[15];
    const float* cls_w2    = (const float*)d_in[16];
    const float* cls_b2    = (const float*)d_in[17];
    const int*   pos       = (const int*)d_in[18];
    const int*   emask     = (const int*)d_in[19];
    float* out = (float*)d_out;

    float  *x, *part;
    __half *xh, *qkvh, *buf1h, *hidh, *wh;
    cudaGetSymbolAddress((void**)&x,     g_x);
    cudaGetSymbolAddress((void**)&xh,    g_xh);
    cudaGetSymbolAddress((void**)&qkvh,  g_qkvh);
    cudaGetSymbolAddress((void**)&buf1h, g_buf1h);
    cudaGetSymbolAddress((void**)&hidh,  g_hidh);
    cudaGetSymbolAddress((void**)&part,  g_part);
    cudaGetSymbolAddress((void**)&wh,    g_wh);

    cudaFuncSetAttribute(gemm_h<128>, cudaFuncAttributeMaxDynamicSharedMemorySize, SMEM_128);
    cudaFuncSetAttribute(gemm_h<64>,  cudaFuncAttributeMaxDynamicSharedMemorySize, SMEM_64);

    // ---- weight conversion (2 kernels) ----
    cvt_all_kernel<<<2048, 256>>>(in_proj_w, out_w, lin1_w, lin2_w, cls_w1, wh);
    cvt_pad_kernel<<<2048, 256>>>(cls_w2, wh + OFF_C2W);

    pool_kernel<<<NT, 128>>>(lhs, attn_w, attn_b, pos, emask, x, xh);

    for (int l = 0; l < Lv; l++) {
        // QKV: 64-row tiles -> 288 blocks, bias fused, fp16 out
        gemm_h<64><<<dim3(18, 16, 1), 256, SMEM_64>>>(
            xh, wh + OFF_IPW + (size_t)l * 3 * Dv * Dv, in_proj_b + (size_t)l * 3 * Dv,
            qkvh, 3 * Dv, Dv, Dv, 2);
        attn_kernel<<<Bv * Hv * 2, 128>>>(qkvh, buf1h);
        // out-proj: split-K 6 -> 288 blocks, reduce rides LN
        gemm_h<128><<<dim3(6, 8, 6), 256, SMEM_128>>>(
            buf1h, wh + OFF_OW + (size_t)l * Dv * Dv, nullptr, part,
            Dv, Dv, 128, 0);
        reduce_addln_kernel<<<NT, 256>>>(x, xh, part, 6, out_b + (size_t)l * Dv,
                                         ln1_w + (size_t)l * Dv, ln1_b + (size_t)l * Dv);
        // lin1: 64-row tiles -> 384 blocks, bias+relu fused, fp16 out
        gemm_h<64><<<dim3(24, 16, 1), 256, SMEM_64>>>(
            xh, wh + OFF_L1W + (size_t)l * DFFv * Dv, lin1_b + (size_t)l * DFFv,
            buf1h, DFFv, Dv, Dv, 3);
        // lin2: K=3072, split-K 6 -> 288 blocks, reduce rides LN
        gemm_h<128><<<dim3(6, 8, 6), 256, SMEM_128>>>(
            buf1h, wh + OFF_L2W + (size_t)l * Dv * DFFv, nullptr, part,
            Dv, DFFv, 512, 0);
        reduce_addln_kernel<<<NT, 256>>>(x, xh, part, 6, lin2_b + (size_t)l * Dv,
                                         ln2_w + (size_t)l * Dv, ln2_b + (size_t)l * Dv);
    }

    // classifier stage 1: split-K 4 -> 32 blocks
    gemm_h<128><<<dim3(1, 8, 4), 256, SMEM_128>>>(
        xh, wh + OFF_C1W, nullptr, part, 100, Dv, 192, 0);
    reduce_hid_kernel<<<512, 256>>>(hidh, part, 4);
    // classifier stage 2: fp32 out, streaming stores
    gemm_h<128><<<dim3(782, 8, 1), 256, SMEM_128>>>(
        hidh, wh + OFF_C2W, cls_b2, out, Ev, 128, 128, 4);
}

// round 16
// speedup vs baseline: 1.0295x; 1.0295x over previous
#include <cuda_runtime.h>
#include <cuda_fp16.h>
#include <math.h>
#include <stdint.h>

// Problem constants
#define Bv   32
#define Sv   512
#define Dv   768
#define Mv   32
#define Tv   30
#define Hv   12
#define HDv  64
#define DFFv 3072
#define Lv   4
#define Ev   100000
#define NT   1024           // B*M token rows

// ---------------- scratch (static device memory; no allocations) -------------
__device__ float  g_x[NT * Dv];            // residual stream (exact fp32)
__device__ __half g_xh[NT * Dv];           // fp16 copy of residual (GEMM A)
__device__ __half g_qkvh[NT * 3 * Dv];     // fp16 QKV (bias fused)
__device__ __half g_buf1h[NT * DFFv];      // attn-out / FF hidden (fp16)
__device__ __half g_hidh[NT * 128];        // classifier hidden, K padded to 128
__device__ float  g_part[2 * NT * DFFv];   // split-K partials (fp32)

// ---- fp16 weight arena: offsets DERIVED from model constants ---------------
#define N_IPW (Lv * 3 * Dv * Dv)
#define N_OW  (Lv * Dv * Dv)
#define N_L1W (Lv * DFFv * Dv)
#define N_L2W (Lv * Dv * DFFv)
#define N_C1W (100 * Dv)
#define N_C2W (Ev * 128)

#define OFF_IPW 0u
#define OFF_OW  ((unsigned)(OFF_IPW + N_IPW))
#define OFF_L1W ((unsigned)(OFF_OW + N_OW))
#define OFF_L2W ((unsigned)(OFF_L1W + N_L1W))
#define OFF_C1W ((unsigned)(OFF_L2W + N_L2W))
#define OFF_C2W ((unsigned)(OFF_C1W + N_C1W))
#define WH_TOTAL ((unsigned)(OFF_C2W + N_C2W))
__device__ __half g_wh[WH_TOTAL];

// chunk (8-elem) boundaries for fused cvt — derived
#define CH_IPW (N_IPW / 8)
#define CH_OW  (CH_IPW + N_OW / 8)
#define CH_L1  (CH_OW + N_L1W / 8)
#define CH_L2  (CH_L1 + N_L2W / 8)
#define CH_C1  (CH_L2 + N_C1W / 8)

// ======================= helpers ============================================
__device__ __forceinline__ void mma_f16(float* c, uint32_t a0, uint32_t a1,
                                        uint32_t a2, uint32_t a3,
                                        uint32_t b0, uint32_t b1) {
    asm volatile(
        "mma.sync.aligned.m16n8k16.row.col.f32.f16.f16.f32 "
        "{%0,%1,%2,%3}, {%4,%5,%6,%7}, {%8,%9}, {%0,%1,%2,%3};"
        : "+f"(c[0]), "+f"(c[1]), "+f"(c[2]), "+f"(c[3])
        : "r"(a0), "r"(a1), "r"(a2), "r"(a3), "r"(b0), "r"(b1));
}

__device__ __forceinline__ void cp16(unsigned dst, const void* src, int bytes) {
    asm volatile("cp.async.ca.shared.global [%0], [%1], 16, %2;\n"
                 :: "r"(dst), "l"(src), "r"(bytes));
}

// ======================= fused weight conversion =============================
__global__ void __launch_bounds__(256) cvt_all_kernel(
    const float* __restrict__ ipw, const float* __restrict__ ow,
    const float* __restrict__ l1w, const float* __restrict__ l2w,
    const float* __restrict__ c1w, __half* __restrict__ wh)
{
    int stride = gridDim.x * blockDim.x;
    for (int i = blockIdx.x * blockDim.x + threadIdx.x; i < CH_C1; i += stride) {
        const float* src;
        __half* dst;
        if (i < CH_IPW)      { src = ipw + (size_t)i * 8;
                               dst = wh + OFF_IPW + (size_t)i * 8; }
        else if (i < CH_OW)  { size_t j = i - CH_IPW; src = ow + j * 8;
                               dst = wh + OFF_OW + j * 8; }
        else if (i < CH_L1)  { size_t j = i - CH_OW;  src = l1w + j * 8;
                               dst = wh + OFF_L1W + j * 8; }
        else if (i < CH_L2)  { size_t j = i - CH_L1;  src = l2w + j * 8;
                               dst = wh + OFF_L2W + j * 8; }
        else                 { size_t j = i - CH_L2;  src = c1w + j * 8;
                               dst = wh + OFF_C1W + j * 8; }
        float4 f0 = *(const float4*)src;
        float4 f1 = *(const float4*)(src + 4);
        __half2 h[4];
        h[0] = __floats2half2_rn(f0.x, f0.y);
        h[1] = __floats2half2_rn(f0.z, f0.w);
        h[2] = __floats2half2_rn(f1.x, f1.y);
        h[3] = __floats2half2_rn(f1.z, f1.w);
        *(uint4*)dst = *(uint4*)h;
    }
}

// cls2 weights [100000,100] -> padded [100000,128] fp16
__global__ void __launch_bounds__(256) cvt_pad_kernel(
    const float* __restrict__ src, __half* __restrict__ dst)
{
    int stride = gridDim.x * blockDim.x;
    const int total = Ev * 32;
    for (int t = blockIdx.x * blockDim.x + threadIdx.x; t < total; t += stride) {
        int r = t >> 5, c4 = (t & 31) * 4;
        __half2 lo, hi;
        if (c4 < 100) {
            float4 f = *(const float4*)(src + (size_t)r * 100 + c4);
            lo = __floats2half2_rn(f.x, f.y);
            hi = __floats2half2_rn(f.z, f.w);
        } else {
            lo = __floats2half2_rn(0.f, 0.f);
            hi = lo;
        }
        __half2 p[2] = { lo, hi };
        *(uint2*)(dst + (size_t)r * 128 + c4) = *(uint2*)p;
    }
}

// ======================= fp16 tensor-core GEMM (3-stage pipeline) ===========
// C = A @ W^T (+bias,+relu). Tile 128x128x32, 256 threads, 8 warps (2x4),
// warp tile 64x32, mma m16n8k16. THREE-stage cp.async ring (wait_group 2,
// uniform commits incl. empty groups). R11-proven fragment mapping.
// mode: bit0 = relu, bit1 = fp16 output, bit2 = streaming stores.
#define HSTRD 48
#define HSMS  (128 * HSTRD)              // halfs per operand stage
#define GEMMH_SMEM (3 * 2 * HSMS * 2)    // 3 stages x (A+B) x 2B = 73728

__device__ __forceinline__ void fill_tiles_h(
    __half* As, __half* Ws, const __half* __restrict__ A,
    const __half* __restrict__ W,
    int rowBase, int colBase, int N, int K, int k0, int kEnd, int tid)
{
    #pragma unroll
    for (int i = 0; i < 2; i++) {
        int c = tid + i * 256;
        int r = c >> 2, ck = c & 3;
        int gk = k0 + ck * 8;
        int ok = (gk < kEnd);
        const __half* src = ok ? (A + (size_t)(rowBase + r) * K + gk) : A;
        unsigned d = (unsigned)__cvta_generic_to_shared(As + r * HSTRD + ck * 8);
        cp16(d, src, ok ? 16 : 0);
    }
    #pragma unroll
    for (int i = 0; i < 2; i++) {
        int c = tid + i * 256;
        int r = c >> 2, ck = c & 3;
        int gk = k0 + ck * 8;
        int n = colBase + r;
        int ok = (n < N) && (gk < kEnd);
        const __half* src = ok ? (W + (size_t)n * K + gk) : W;
        unsigned d = (unsigned)__cvta_generic_to_shared(Ws + r * HSTRD + ck * 8);
        cp16(d, src, ok ? 16 : 0);
    }
}

__global__ void __launch_bounds__(256, 2) gemm_h(
    const __half* __restrict__ A, const __half* __restrict__ W,
    const float* __restrict__ bias, void* Cv,
    int N, int K, int kChunk, int mode)
{
    extern __shared__ __half hs[];
    // ring layout: stage s -> A at hs + s*2*HSMS, W at hs + s*2*HSMS + HSMS
    const int tid = threadIdx.x;
    const int lane = tid & 31, wid = tid >> 5;
    const int wy = wid >> 2, wx = wid & 3;
    const int lm = lane >> 2, lk = lane & 3;
    const int rowBase = blockIdx.y * 128;
    const int colBase = blockIdx.x * 128;
    const int kBase = blockIdx.z * kChunk;
    const int kEnd = min(K, kBase + kChunk);
    const int nT = (kEnd - kBase + 31) >> 5;

    float acc[4][4][4];
    #pragma unroll
    for (int i = 0; i < 4; i++)
        #pragma unroll
        for (int j = 0; j < 4; j++)
            #pragma unroll
            for (int q = 0; q < 4; q++) acc[i][j][q] = 0.f;

    // prologue: tiles 0 and 1 (empty commit if absent -> uniform accounting)
    fill_tiles_h(hs, hs + HSMS, A, W, rowBase, colBase, N, K, kBase, kEnd, tid);
    asm volatile("cp.async.commit_group;\n" ::: "memory");
    if (1 < nT)
        fill_tiles_h(hs + 2 * HSMS, hs + 3 * HSMS, A, W, rowBase, colBase,
                     N, K, kBase + 32, kEnd, tid);
    asm volatile("cp.async.commit_group;\n" ::: "memory");

    for (int t = 0; t < nT; t++) {
        // issue tile t+2 into ring slot (t+2)%3 (freed by compute(t-1) last iter)
        if (t + 2 < nT) {
            int s = (t + 2) % 3;
            fill_tiles_h(hs + s * 2 * HSMS, hs + s * 2 * HSMS + HSMS,
                         A, W, rowBase, colBase, N, K, kBase + (t + 2) * 32, kEnd, tid);
        }
        asm volatile("cp.async.commit_group;\n" ::: "memory");
        // groups committed so far: t+3; wait until <=2 outstanding -> tile t done
        asm volatile("cp.async.wait_group 2;\n" ::: "memory");
        __syncthreads();

        const int cs = t % 3;
        const __half* as = hs + cs * 2 * HSMS;
        const __half* ws = as + HSMS;
        #pragma unroll
        for (int ks = 0; ks < 2; ks++) {
            const int kb = ks * 16;
            uint2 afr[4][2];
            #pragma unroll
            for (int mt = 0; mt < 4; mt++) {
                int m = wy * 64 + mt * 16 + lm;
                afr[mt][0] = *(const uint2*)(as + m * HSTRD + kb + 4 * lk);
                afr[mt][1] = *(const uint2*)(as + (m + 8) * HSTRD + kb + 4 * lk);
            }
            uint2 bfr[4];
            #pragma unroll
            for (int nt = 0; nt < 4; nt++) {
                int n = wx * 32 + nt * 8 + lm;
                bfr[nt] = *(const uint2*)(ws + n * HSTRD + kb + 4 * lk);
            }
            #pragma unroll
            for (int mt = 0; mt < 4; mt++)
                #pragma unroll
                for (int nt = 0; nt < 4; nt++)
                    mma_f16(acc[mt][nt],
                            afr[mt][0].x, afr[mt][1].x,
                            afr[mt][0].y, afr[mt][1].y,
                            bfr[nt].x, bfr[nt].y);
        }
        __syncthreads();
    }

    // ======== smem-staged epilogue ========
    const int relu = mode & 1, halfOut = mode & 2, streamC = mode & 4;

    if (!halfOut) {
        float* Cf = (float*)Cv;
        if (gridDim.z > 1) Cf += (size_t)blockIdx.z * ((size_t)NT * N);
        float* sf = (float*)hs;
        #pragma unroll
        for (int ph = 0; ph < 2; ph++) {
            if (wy == ph) {
                #pragma unroll
                for (int mt = 0; mt < 4; mt++) {
                    #pragma unroll
                    for (int nt = 0; nt < 4; nt++) {
                        int lr = mt * 16 + lm;
                        int c0 = wx * 32 + nt * 8 + lk * 2;
                        int gc = colBase + c0;
                        float bx = 0.f, by = 0.f;
                        if (bias) {
                            if (gc < N)     bx = bias[gc];
                            if (gc + 1 < N) by = bias[gc + 1];
                        }
                        float v00 = acc[mt][nt][0] + bx, v01 = acc[mt][nt][1] + by;
                        float v10 = acc[mt][nt][2] + bx, v11 = acc[mt][nt][3] + by;
                        if (relu) {
                            v00 = fmaxf(v00, 0.f); v01 = fmaxf(v01, 0.f);
                            v10 = fmaxf(v10, 0.f); v11 = fmaxf(v11, 0.f);
                        }
                        *(float2*)(sf + lr * 132 + c0)       = make_float2(v00, v01);
                        *(float2*)(sf + (lr + 8) * 132 + c0) = make_float2(v10, v11);
                    }
                }
            }
            __syncthreads();
            int gRowBase = rowBase + ph * 64;
            #pragma unroll
            for (int it = 0; it < 8; it++) {
                int fidx = tid + it * 256;
                int row  = fidx >> 5;
                int col4 = (fidx & 31) << 2;
                float4 v = *(const float4*)(sf + row * 132 + col4);
                int gc = colBase + col4;
                float* dst = Cf + (size_t)(gRowBase + row) * N + gc;
                if (gc + 3 < N) {
                    if (streamC) __stcs((float4*)dst, v);
                    else         *(float4*)dst = v;
                } else {
                    if (gc < N)     dst[0] = v.x;
                    if (gc + 1 < N) dst[1] = v.y;
                    if (gc + 2 < N) dst[2] = v.z;
                }
            }
            __syncthreads();
        }
    } else {
        __half* Ch = (__half*)Cv;
        __half* sh2 = hs;
        #pragma unroll
        for (int mt = 0; mt < 4; mt++) {
            #pragma unroll
            for (int nt = 0; nt < 4; nt++) {
                int lr = wy * 64 + mt * 16 + lm;
                int c0 = wx * 32 + nt * 8 + lk * 2;
                int gc = colBase + c0;
                float bx = 0.f, by = 0.f;
                if (bias) {
                    if (gc < N)     bx = bias[gc];
                    if (gc + 1 < N) by = bias[gc + 1];
                }
                float v00 = acc[mt][nt][0] + bx, v01 = acc[mt][nt][1] + by;
                float v10 = acc[mt][nt][2] + bx, v11 = acc[mt][nt][3] + by;
                if (relu) {
                    v00 = fmaxf(v00, 0.f); v01 = fmaxf(v01, 0.f);
                    v10 = fmaxf(v10, 0.f); v11 = fmaxf(v11, 0.f);
                }
                *(__half2*)(sh2 + lr * 136 + c0)       = __floats2half2_rn(v00, v01);
                *(__half2*)(sh2 + (lr + 8) * 136 + c0) = __floats2half2_rn(v10, v11);
            }
        }
        __syncthreads();
        #pragma unroll
        for (int it = 0; it < 8; it++) {
            int fidx = tid + it * 256;
            int row  = fidx >> 4;
            int col8 = (fidx & 15) << 3;
            uint4 v = *(const uint4*)(sh2 + row * 136 + col8);
            int gc = colBase + col8;
            __half* dst = Ch + (size_t)(rowBase + row) * N + gc;
            if (gc + 7 < N) {
                *(uint4*)dst = v;
            } else {
                const __half* sv = sh2 + row * 136 + col8;
                for (int j = 0; j < 8; j++)
                    if (gc + j < N) dst[j] = sv[j];
            }
        }
    }
}

// ======================= mention pooling ====================================
__global__ void __launch_bounds__(128) pool_kernel(
    const float* __restrict__ lhs, const float* __restrict__ attn_w,
    const float* __restrict__ attn_b_p, const int* __restrict__ pos,
    const int* __restrict__ emask, float* __restrict__ x, __half* __restrict__ xh)
{
    int bm = blockIdx.x;
    int b = bm / Mv;
    __shared__ float logit[Tv];
    __shared__ float score[Tv];
    __shared__ int   validv[Tv];

    int tid = threadIdx.x, lane = tid & 31, warp = tid >> 5;

    if (tid == 0) {
        int ok = (emask[bm] != 0);
        int alive = 1;
        for (int t = 0; t < Tv; t++) {
            if (pos[bm * Tv + t] == -1) alive = 0;
            validv[t] = ok & alive;
        }
    }
    __syncthreads();

    float ab = attn_b_p[0];
    const float* lb = lhs + (size_t)b * Sv * Dv;

    for (int t = warp; t < Tv; t += 4) {
        float s = 0.f;
        for (int d = lane; d < Dv; d += 32) s += lb[t * Dv + d] * attn_w[d];
        for (int o = 16; o; o >>= 1) s += __shfl_xor_sync(0xffffffffu, s, o);
        if (lane == 0) logit[t] = (validv[t] ? s : 0.f) + ab;
    }
    __syncthreads();

    if (tid < 32) {
        float v = (tid < Tv) ? logit[tid] : -INFINITY;
        float mx = v;
        for (int o = 16; o; o >>= 1) mx = fmaxf(mx, __shfl_xor_sync(0xffffffffu, mx, o));
        float e = (tid < Tv) ? expf(v - mx) : 0.f;
        float sm = e;
        for (int o = 16; o; o >>= 1) sm += __shfl_xor_sync(0xffffffffu, sm, o);
        if (tid < Tv) score[tid] = e / sm;
    }
    __syncthreads();

    for (int d = tid; d < Dv; d += 128) {
        float s = 0.f;
        #pragma unroll
        for (int t = 0; t < Tv; t++)
            if (validv[t]) s += score[t] * lb[t * Dv + d];
        x[(size_t)bm * Dv + d]  = s;
        xh[(size_t)bm * Dv + d] = __float2half_rn(s);
    }
}

// ======= attention: reads fp16 qkv (bias already fused) =====================
__global__ void __launch_bounds__(128) attn_kernel(
    const __half* __restrict__ qkv, __half* __restrict__ o)
{
    const int bh = blockIdx.x >> 1;
    const int half_ = blockIdx.x & 1;
    const int b = bh / Hv, h = bh % Hv;
    const int r0 = half_ * 16;

    __shared__ float q[16][68];
    __shared__ float kk[32][68];
    __shared__ float vv[32][68];
    __shared__ float a[16][33];

    const int tid = threadIdx.x;
    const __half* base = qkv + (size_t)(b * Mv) * (3 * Dv) + h * HDv;

    #pragma unroll
    for (int rep = 0; rep < 4; rep++) {
        int idx = tid + rep * 128;
        int i = idx >> 5, d2 = idx & 31;
        __half2 v = *(const __half2*)(base + (size_t)(r0 + i) * (3 * Dv) + d2 * 2);
        float2 f = __half22float2(v);
        q[i][d2 * 2]     = f.x;
        q[i][d2 * 2 + 1] = f.y;
    }
    #pragma unroll
    for (int rep = 0; rep < 8; rep++) {
        int idx = tid + rep * 128;
        int i = idx >> 5, d2 = idx & 31;
        size_t off = (size_t)i * (3 * Dv) + d2 * 2;
        float2 fk = __half22float2(*(const __half2*)(base + off + Dv));
        float2 fv = __half22float2(*(const __half2*)(base + off + 2 * Dv));
        kk[i][d2 * 2]     = fk.x;
        kk[i][d2 * 2 + 1] = fk.y;
        vv[i][d2 * 2]     = fv.x;
        vv[i][d2 * 2 + 1] = fv.y;
    }
    __syncthreads();

    #pragma unroll
    for (int rep = 0; rep < 4; rep++) {
        int idx = tid + rep * 128;
        int i = idx >> 5, j = idx & 31;
        float s = 0.f;
        #pragma unroll
        for (int d = 0; d < 64; d += 4) {
            float4 qa = *(const float4*)&q[i][d];
            float4 ka = *(const float4*)&kk[j][d];
            s += qa.x * ka.x + qa.y * ka.y + qa.z * ka.z + qa.w * ka.w;
        }
        a[i][j] = s * 0.125f;
    }
    __syncthreads();

    int warp = tid >> 5, lane = tid & 31;
    #pragma unroll
    for (int r = 0; r < 4; r++) {
        int i = warp * 4 + r;
        float v = a[i][lane];
        float mx = v;
        for (int off = 16; off; off >>= 1) mx = fmaxf(mx, __shfl_xor_sync(0xffffffffu, mx, off));
        float e = expf(v - mx);
        float sm = e;
        for (int off = 16; off; off >>= 1) sm += __shfl_xor_sync(0xffffffffu, sm, off);
        a[i][lane] = e / sm;
    }
    __syncthreads();

    __half* obase = o + (size_t)(b * Mv + r0) * Dv + h * HDv;
    #pragma unroll
    for (int rep = 0; rep < 8; rep++) {
        int idx = tid + rep * 128;
        int i = idx >> 6, d = idx & 63;
        float s = 0.f;
        #pragma unroll
        for (int j = 0; j < 32; j++) s += a[i][j] * vv[j][d];
        obase[(size_t)i * Dv + d] = __float2half_rn(s);
    }
}

// ===== reduce cls1 split-K partials -> padded fp16 hid [1024][128] ==========
__global__ void __launch_bounds__(256) reduce_hid_kernel(
    __half* __restrict__ dst, const float* __restrict__ part, int nPart)
{
    const size_t total = (size_t)NT * 100;
    const size_t stride = (size_t)gridDim.x * blockDim.x;
    for (size_t idx = (size_t)blockIdx.x * blockDim.x + threadIdx.x;
         idx < total; idx += stride) {
        float s = 0.f;
        for (int p = 0; p < nPart; p++) s += part[(size_t)p * total + idx];
        size_t row = idx / 100, col = idx % 100;
        dst[row * 128 + col] = __float2half_rn(s);
    }
}

// ===== reduce split-K partials + bias + residual add + LayerNorm ============
__global__ void __launch_bounds__(256) reduce_addln_kernel(
    float* __restrict__ x, __half* __restrict__ xh,
    const float* __restrict__ part, int nPart,
    const float* __restrict__ bias,
    const float* __restrict__ w, const float* __restrict__ b)
{
    __shared__ float sh[8];
    __shared__ float s_mean, s_inv;
    const int row = blockIdx.x;
    float* xr = x + (size_t)row * Dv;
    __half* xt = xh + (size_t)row * Dv;
    const int tid = threadIdx.x, lane = tid & 31, warp = tid >> 5;
    const size_t planeStride = (size_t)NT * Dv;

    float v[3];
    float sum = 0.f;
    #pragma unroll
    for (int i = 0; i < 3; i++) {
        int idx = tid + 256 * i;
        float d = bias[idx];
        for (int p = 0; p < nPart; p++)
            d += part[(size_t)p * planeStride + (size_t)row * Dv + idx];
        v[i] = xr[idx] + d;
        sum += v[i];
    }
    for (int o = 16; o; o >>= 1) sum += __shfl_xor_sync(0xffffffffu, sum, o);
    if (lane == 0) sh[warp] = sum;
    __syncthreads();
    if (tid == 0) {
        float s = 0.f;
        for (int i = 0; i < 8; i++) s += sh[i];
        s_mean = s * (1.f / (float)Dv);
    }
    __syncthreads();
    float mean = s_mean;

    float sq = 0.f;
    #pragma unroll
    for (int i = 0; i < 3; i++) { float c = v[i] - mean; sq += c * c; }
    for (int o = 16; o; o >>= 1) sq += __shfl_xor_sync(0xffffffffu, sq, o);
    if (lane == 0) sh[warp] = sq;
    __syncthreads();
    if (tid == 0) {
        float s = 0.f;
        for (int i = 0; i < 8; i++) s += sh[i];
        s_inv = rsqrtf(s * (1.f / (float)Dv) + 1e-5f);
    }
    __syncthreads();
    float inv = s_inv;

    #pragma unroll
    for (int i = 0; i < 3; i++) {
        int idx = tid + 256 * i;
        float o = (v[i] - mean) * inv * w[idx] + b[idx];
        xr[idx] = o;
        xt[idx] = __float2half_rn(o);
    }
}

// ======================= launcher ===========================================
extern "C" void kernel_launch(void* const* d_in, const int* in_sizes, int n_in,
                              void* d_out, int out_size)
{
    const float* lhs       = (const float*)d_in[0];
    const float* attn_w    = (const float*)d_in[1];
    const float* attn_b    = (const float*)d_in[2];
    const float* in_proj_w = (const float*)d_in[3];
    const float* in_proj_b = (const float*)d_in[4];
    const float* out_w     = (const float*)d_in[5];
    const float* out_b     = (const float*)d_in[6];
    const float* ln1_w     = (const float*)d_in[7];
    const float* ln1_b     = (const float*)d_in[8];
    const float* lin1_w    = (const float*)d_in[9];
    const float* lin1_b    = (const float*)d_in[10];
    const float* lin2_w    = (const float*)d_in[11];
    const float* lin2_b    = (const float*)d_in[12];
    const float* ln2_w     = (const float*)d_in[13];
    const float* ln2_b     = (const float*)d_in[14];
    const float* cls_w1    = (const float*)d_in[15];
    const float* cls_w2    = (const float*)d_in[16];
    const float* cls_b2    = (const float*)d_in[17];
    const int*   pos       = (const int*)d_in[18];
    const int*   emask     = (const int*)d_in[19];
    float* out = (float*)d_out;

    float  *x, *part;
    __half *xh, *qkvh, *buf1h, *hidh, *wh;
    cudaGetSymbolAddress((void**)&x,     g_x);
    cudaGetSymbolAddress((void**)&xh,    g_xh);
    cudaGetSymbolAddress((void**)&qkvh,  g_qkvh);
    cudaGetSymbolAddress((void**)&buf1h, g_buf1h);
    cudaGetSymbolAddress((void**)&hidh,  g_hidh);
    cudaGetSymbolAddress((void**)&part,  g_part);
    cudaGetSymbolAddress((void**)&wh,    g_wh);

    cudaFuncSetAttribute(gemm_h, cudaFuncAttributeMaxDynamicSharedMemorySize, GEMMH_SMEM);

    // ---- weight conversion (2 kernels) ----
    cvt_all_kernel<<<2048, 256>>>(in_proj_w, out_w, lin1_w, lin2_w, cls_w1, wh);
    cvt_pad_kernel<<<2048, 256>>>(cls_w2, wh + OFF_C2W);

    pool_kernel<<<NT, 128>>>(lhs, attn_w, attn_b, pos, emask, x, xh);

    for (int l = 0; l < Lv; l++) {
        // QKV: no split, bias fused, fp16 out -> 144 blocks
        gemm_h<<<dim3(18, 8, 1), 256, GEMMH_SMEM>>>(
            xh, wh + OFF_IPW + (size_t)l * 3 * Dv * Dv, in_proj_b + (size_t)l * 3 * Dv,
            qkvh, 3 * Dv, Dv, Dv, 2);
        attn_kernel<<<Bv * Hv * 2, 128>>>(qkvh, buf1h);
        // out-proj: split-K 6 -> 288 blocks, reduce rides LN
        gemm_h<<<dim3(6, 8, 6), 256, GEMMH_SMEM>>>(
            buf1h, wh + OFF_OW + (size_t)l * Dv * Dv, nullptr, part,
            Dv, Dv, 128, 0);
        reduce_addln_kernel<<<NT, 256>>>(x, xh, part, 6, out_b + (size_t)l * Dv,
                                         ln1_w + (size_t)l * Dv, ln1_b + (size_t)l * Dv);
        // lin1: no split, bias+relu fused, fp16 out -> 192 blocks
        gemm_h<<<dim3(24, 8, 1), 256, GEMMH_SMEM>>>(
            xh, wh + OFF_L1W + (size_t)l * DFFv * Dv, lin1_b + (size_t)l * DFFv,
            buf1h, DFFv, Dv, Dv, 3);
        // lin2: K=3072, split-K 6 -> 288 blocks, reduce rides LN
        gemm_h<<<dim3(6, 8, 6), 256, GEMMH_SMEM>>>(
            buf1h, wh + OFF_L2W + (size_t)l * Dv * DFFv, nullptr, part,
            Dv, DFFv, 512, 0);
        reduce_addln_kernel<<<NT, 256>>>(x, xh, part, 6, lin2_b + (size_t)l * Dv,
                                         ln2_w + (size_t)l * Dv, ln2_b + (size_t)l * Dv);
    }

    // classifier stage 1: split-K 4 -> 32 blocks
    gemm_h<<<dim3(1, 8, 4), 256, GEMMH_SMEM>>>(
        xh, wh + OFF_C1W, nullptr, part, 100, Dv, 192, 0);
    reduce_hid_kernel<<<512, 256>>>(hidh, part, 4);
    // classifier stage 2: fp32 out, streaming stores
    gemm_h<<<dim3(782, 8, 1), 256, GEMMH_SMEM>>>(
        hidh, wh + OFF_C2W, cls_b2, out, Ev, 128, 128, 4);
}

// round 17
// speedup vs baseline: 1.0483x; 1.0183x over previous
#include <cuda_runtime.h>
#include <cuda_fp16.h>
#include <math.h>
#include <stdint.h>

// Problem constants
#define Bv   32
#define Sv   512
#define Dv   768
#define Mv   32
#define Tv   30
#define Hv   12
#define HDv  64
#define DFFv 3072
#define Lv   4
#define Ev   100000
#define NT   1024           // B*M token rows

// ---------------- scratch (static device memory; no allocations) -------------
__device__ float  g_x[NT * Dv];            // residual stream (exact fp32)
__device__ __half g_xh[NT * Dv];           // fp16 copy of residual (GEMM A)
__device__ __half g_buf1h[NT * DFFv];      // attn-out / FF hidden (fp16)
__device__ __half g_hidh[NT * 128];        // classifier hidden, K padded to 128
__device__ float  g_part[2 * NT * DFFv];   // split-K partials (fp32 or fp16 planes)

// ---- fp16 weight arena: offsets DERIVED from model constants ---------------
#define N_IPW (Lv * 3 * Dv * Dv)
#define N_OW  (Lv * Dv * Dv)
#define N_L1W (Lv * DFFv * Dv)
#define N_L2W (Lv * Dv * DFFv)
#define N_C1W (100 * Dv)
#define N_C2W (Ev * 128)

#define OFF_IPW 0u
#define OFF_OW  ((unsigned)(OFF_IPW + N_IPW))
#define OFF_L1W ((unsigned)(OFF_OW + N_OW))
#define OFF_L2W ((unsigned)(OFF_L1W + N_L1W))
#define OFF_C1W ((unsigned)(OFF_L2W + N_L2W))
#define OFF_C2W ((unsigned)(OFF_C1W + N_C1W))
#define WH_TOTAL ((unsigned)(OFF_C2W + N_C2W))
__device__ __half g_wh[WH_TOTAL];

// chunk (8-elem) boundaries for fused cvt — derived
#define CH_IPW (N_IPW / 8)
#define CH_OW  (CH_IPW + N_OW / 8)
#define CH_L1  (CH_OW + N_L1W / 8)
#define CH_L2  (CH_L1 + N_L2W / 8)
#define CH_C1  (CH_L2 + N_C1W / 8)

// ======================= helpers ============================================
__device__ __forceinline__ void mma_f16(float* c, uint32_t a0, uint32_t a1,
                                        uint32_t a2, uint32_t a3,
                                        uint32_t b0, uint32_t b1) {
    asm volatile(
        "mma.sync.aligned.m16n8k16.row.col.f32.f16.f16.f32 "
        "{%0,%1,%2,%3}, {%4,%5,%6,%7}, {%8,%9}, {%0,%1,%2,%3};"
        : "+f"(c[0]), "+f"(c[1]), "+f"(c[2]), "+f"(c[3])
        : "r"(a0), "r"(a1), "r"(a2), "r"(a3), "r"(b0), "r"(b1));
}

__device__ __forceinline__ void cp16(unsigned dst, const void* src, int bytes) {
    asm volatile("cp.async.ca.shared.global [%0], [%1], 16, %2;\n"
                 :: "r"(dst), "l"(src), "r"(bytes));
}

// ======================= fused weight conversion =============================
__global__ void __launch_bounds__(256) cvt_all_kernel(
    const float* __restrict__ ipw, const float* __restrict__ ow,
    const float* __restrict__ l1w, const float* __restrict__ l2w,
    const float* __restrict__ c1w, __half* __restrict__ wh)
{
    int stride = gridDim.x * blockDim.x;
    for (int i = blockIdx.x * blockDim.x + threadIdx.x; i < CH_C1; i += stride) {
        const float* src;
        __half* dst;
        if (i < CH_IPW)      { src = ipw + (size_t)i * 8;
                               dst = wh + OFF_IPW + (size_t)i * 8; }
        else if (i < CH_OW)  { size_t j = i - CH_IPW; src = ow + j * 8;
                               dst = wh + OFF_OW + j * 8; }
        else if (i < CH_L1)  { size_t j = i - CH_OW;  src = l1w + j * 8;
                               dst = wh + OFF_L1W + j * 8; }
        else if (i < CH_L2)  { size_t j = i - CH_L1;  src = l2w + j * 8;
                               dst = wh + OFF_L2W + j * 8; }
        else                 { size_t j = i - CH_L2;  src = c1w + j * 8;
                               dst = wh + OFF_C1W + j * 8; }
        float4 f0 = *(const float4*)src;
        float4 f1 = *(const float4*)(src + 4);
        __half2 h[4];
        h[0] = __floats2half2_rn(f0.x, f0.y);
        h[1] = __floats2half2_rn(f0.z, f0.w);
        h[2] = __floats2half2_rn(f1.x, f1.y);
        h[3] = __floats2half2_rn(f1.z, f1.w);
        *(uint4*)dst = *(uint4*)h;
    }
}

// cls2 weights [100000,100] -> padded [100000,128] fp16
__global__ void __launch_bounds__(256) cvt_pad_kernel(
    const float* __restrict__ src, __half* __restrict__ dst)
{
    int stride = gridDim.x * blockDim.x;
    const int total = Ev * 32;
    for (int t = blockIdx.x * blockDim.x + threadIdx.x; t < total; t += stride) {
        int r = t >> 5, c4 = (t & 31) * 4;
        __half2 lo, hi;
        if (c4 < 100) {
            float4 f = *(const float4*)(src + (size_t)r * 100 + c4);
            lo = __floats2half2_rn(f.x, f.y);
            hi = __floats2half2_rn(f.z, f.w);
        } else {
            lo = __floats2half2_rn(0.f, 0.f);
            hi = lo;
        }
        __half2 p[2] = { lo, hi };
        *(uint2*)(dst + (size_t)r * 128 + c4) = *(uint2*)p;
    }
}

// ======================= fp16 tensor-core GEMM (3-stage pipeline) ===========
// mode: bit0 = relu, bit1 = fp16 output, bit2 = streaming stores.
// fp16 output + gridDim.z>1 -> fp16 split-K partial planes (stride NT*N halfs).
#define HSTRD 48
#define HSMS  (128 * HSTRD)              // halfs per operand stage
#define GEMMH_SMEM (3 * 2 * HSMS * 2)    // 3 stages x (A+B) x 2B = 73728

__device__ __forceinline__ void fill_tiles_h(
    __half* As, __half* Ws, const __half* __restrict__ A,
    const __half* __restrict__ W,
    int rowBase, int colBase, int N, int K, int k0, int kEnd, int tid)
{
    #pragma unroll
    for (int i = 0; i < 2; i++) {
        int c = tid + i * 256;
        int r = c >> 2, ck = c & 3;
        int gk = k0 + ck * 8;
        int ok = (gk < kEnd);
        const __half* src = ok ? (A + (size_t)(rowBase + r) * K + gk) : A;
        unsigned d = (unsigned)__cvta_generic_to_shared(As + r * HSTRD + ck * 8);
        cp16(d, src, ok ? 16 : 0);
    }
    #pragma unroll
    for (int i = 0; i < 2; i++) {
        int c = tid + i * 256;
        int r = c >> 2, ck = c & 3;
        int gk = k0 + ck * 8;
        int n = colBase + r;
        int ok = (n < N) && (gk < kEnd);
        const __half* src = ok ? (W + (size_t)n * K + gk) : W;
        unsigned d = (unsigned)__cvta_generic_to_shared(Ws + r * HSTRD + ck * 8);
        cp16(d, src, ok ? 16 : 0);
    }
}

__global__ void __launch_bounds__(256, 2) gemm_h(
    const __half* __restrict__ A, const __half* __restrict__ W,
    const float* __restrict__ bias, void* Cv,
    int N, int K, int kChunk, int mode)
{
    extern __shared__ __half hs[];
    const int tid = threadIdx.x;
    const int lane = tid & 31, wid = tid >> 5;
    const int wy = wid >> 2, wx = wid & 3;
    const int lm = lane >> 2, lk = lane & 3;
    const int rowBase = blockIdx.y * 128;
    const int colBase = blockIdx.x * 128;
    const int kBase = blockIdx.z * kChunk;
    const int kEnd = min(K, kBase + kChunk);
    const int nT = (kEnd - kBase + 31) >> 5;

    float acc[4][4][4];
    #pragma unroll
    for (int i = 0; i < 4; i++)
        #pragma unroll
        for (int j = 0; j < 4; j++)
            #pragma unroll
            for (int q = 0; q < 4; q++) acc[i][j][q] = 0.f;

    fill_tiles_h(hs, hs + HSMS, A, W, rowBase, colBase, N, K, kBase, kEnd, tid);
    asm volatile("cp.async.commit_group;\n" ::: "memory");
    if (1 < nT)
        fill_tiles_h(hs + 2 * HSMS, hs + 3 * HSMS, A, W, rowBase, colBase,
                     N, K, kBase + 32, kEnd, tid);
    asm volatile("cp.async.commit_group;\n" ::: "memory");

    for (int t = 0; t < nT; t++) {
        if (t + 2 < nT) {
            int s = (t + 2) % 3;
            fill_tiles_h(hs + s * 2 * HSMS, hs + s * 2 * HSMS + HSMS,
                         A, W, rowBase, colBase, N, K, kBase + (t + 2) * 32, kEnd, tid);
        }
        asm volatile("cp.async.commit_group;\n" ::: "memory");
        asm volatile("cp.async.wait_group 2;\n" ::: "memory");
        __syncthreads();

        const int cs = t % 3;
        const __half* as = hs + cs * 2 * HSMS;
        const __half* ws = as + HSMS;
        #pragma unroll
        for (int ks = 0; ks < 2; ks++) {
            const int kb = ks * 16;
            uint2 afr[4][2];
            #pragma unroll
            for (int mt = 0; mt < 4; mt++) {
                int m = wy * 64 + mt * 16 + lm;
                afr[mt][0] = *(const uint2*)(as + m * HSTRD + kb + 4 * lk);
                afr[mt][1] = *(const uint2*)(as + (m + 8) * HSTRD + kb + 4 * lk);
            }
            uint2 bfr[4];
            #pragma unroll
            for (int nt = 0; nt < 4; nt++) {
                int n = wx * 32 + nt * 8 + lm;
                bfr[nt] = *(const uint2*)(ws + n * HSTRD + kb + 4 * lk);
            }
            #pragma unroll
            for (int mt = 0; mt < 4; mt++)
                #pragma unroll
                for (int nt = 0; nt < 4; nt++)
                    mma_f16(acc[mt][nt],
                            afr[mt][0].x, afr[mt][1].x,
                            afr[mt][0].y, afr[mt][1].y,
                            bfr[nt].x, bfr[nt].y);
        }
        __syncthreads();
    }

    // ======== smem-staged epilogue ========
    const int relu = mode & 1, halfOut = mode & 2, streamC = mode & 4;

    if (!halfOut) {
        float* Cf = (float*)Cv;
        if (gridDim.z > 1) Cf += (size_t)blockIdx.z * ((size_t)NT * N);
        float* sf = (float*)hs;
        #pragma unroll
        for (int ph = 0; ph < 2; ph++) {
            if (wy == ph) {
                #pragma unroll
                for (int mt = 0; mt < 4; mt++) {
                    #pragma unroll
                    for (int nt = 0; nt < 4; nt++) {
                        int lr = mt * 16 + lm;
                        int c0 = wx * 32 + nt * 8 + lk * 2;
                        int gc = colBase + c0;
                        float bx = 0.f, by = 0.f;
                        if (bias) {
                            if (gc < N)     bx = bias[gc];
                            if (gc + 1 < N) by = bias[gc + 1];
                        }
                        float v00 = acc[mt][nt][0] + bx, v01 = acc[mt][nt][1] + by;
                        float v10 = acc[mt][nt][2] + bx, v11 = acc[mt][nt][3] + by;
                        if (relu) {
                            v00 = fmaxf(v00, 0.f); v01 = fmaxf(v01, 0.f);
                            v10 = fmaxf(v10, 0.f); v11 = fmaxf(v11, 0.f);
                        }
                        *(float2*)(sf + lr * 132 + c0)       = make_float2(v00, v01);
                        *(float2*)(sf + (lr + 8) * 132 + c0) = make_float2(v10, v11);
                    }
                }
            }
            __syncthreads();
            int gRowBase = rowBase + ph * 64;
            #pragma unroll
            for (int it = 0; it < 8; it++) {
                int fidx = tid + it * 256;
                int row  = fidx >> 5;
                int col4 = (fidx & 31) << 2;
                float4 v = *(const float4*)(sf + row * 132 + col4);
                int gc = colBase + col4;
                float* dst = Cf + (size_t)(gRowBase + row) * N + gc;
                if (gc + 3 < N) {
                    if (streamC) __stcs((float4*)dst, v);
                    else         *(float4*)dst = v;
                } else {
                    if (gc < N)     dst[0] = v.x;
                    if (gc + 1 < N) dst[1] = v.y;
                    if (gc + 2 < N) dst[2] = v.z;
                }
            }
            __syncthreads();
        }
    } else {
        __half* Ch = (__half*)Cv;
        if (gridDim.z > 1) Ch += (size_t)blockIdx.z * ((size_t)NT * N);
        __half* sh2 = hs;
        #pragma unroll
        for (int mt = 0; mt < 4; mt++) {
            #pragma unroll
            for (int nt = 0; nt < 4; nt++) {
                int lr = wy * 64 + mt * 16 + lm;
                int c0 = wx * 32 + nt * 8 + lk * 2;
                int gc = colBase + c0;
                float bx = 0.f, by = 0.f;
                if (bias) {
                    if (gc < N)     bx = bias[gc];
                    if (gc + 1 < N) by = bias[gc + 1];
                }
                float v00 = acc[mt][nt][0] + bx, v01 = acc[mt][nt][1] + by;
                float v10 = acc[mt][nt][2] + bx, v11 = acc[mt][nt][3] + by;
                if (relu) {
                    v00 = fmaxf(v00, 0.f); v01 = fmaxf(v01, 0.f);
                    v10 = fmaxf(v10, 0.f); v11 = fmaxf(v11, 0.f);
                }
                *(__half2*)(sh2 + lr * 136 + c0)       = __floats2half2_rn(v00, v01);
                *(__half2*)(sh2 + (lr + 8) * 136 + c0) = __floats2half2_rn(v10, v11);
            }
        }
        __syncthreads();
        #pragma unroll
        for (int it = 0; it < 8; it++) {
            int fidx = tid + it * 256;
            int row  = fidx >> 4;
            int col8 = (fidx & 15) << 3;
            uint4 v = *(const uint4*)(sh2 + row * 136 + col8);
            int gc = colBase + col8;
            __half* dst = Ch + (size_t)(rowBase + row) * N + gc;
            if (gc + 7 < N) {
                *(uint4*)dst = v;
            } else {
                const __half* sv = sh2 + row * 136 + col8;
                for (int j = 0; j < 8; j++)
                    if (gc + j < N) dst[j] = sv[j];
            }
        }
    }
}

// ======================= mention pooling ====================================
__global__ void __launch_bounds__(128) pool_kernel(
    const float* __restrict__ lhs, const float* __restrict__ attn_w,
    const float* __restrict__ attn_b_p, const int* __restrict__ pos,
    const int* __restrict__ emask, float* __restrict__ x, __half* __restrict__ xh)
{
    int bm = blockIdx.x;
    int b = bm / Mv;
    __shared__ float logit[Tv];
    __shared__ float score[Tv];
    __shared__ int   validv[Tv];

    int tid = threadIdx.x, lane = tid & 31, warp = tid >> 5;

    if (tid == 0) {
        int ok = (emask[bm] != 0);
        int alive = 1;
        for (int t = 0; t < Tv; t++) {
            if (pos[bm * Tv + t] == -1) alive = 0;
            validv[t] = ok & alive;
        }
    }
    __syncthreads();

    float ab = attn_b_p[0];
    const float* lb = lhs + (size_t)b * Sv * Dv;

    for (int t = warp; t < Tv; t += 4) {
        float s = 0.f;
        for (int d = lane; d < Dv; d += 32) s += lb[t * Dv + d] * attn_w[d];
        for (int o = 16; o; o >>= 1) s += __shfl_xor_sync(0xffffffffu, s, o);
        if (lane == 0) logit[t] = (validv[t] ? s : 0.f) + ab;
    }
    __syncthreads();

    if (tid < 32) {
        float v = (tid < Tv) ? logit[tid] : -INFINITY;
        float mx = v;
        for (int o = 16; o; o >>= 1) mx = fmaxf(mx, __shfl_xor_sync(0xffffffffu, mx, o));
        float e = (tid < Tv) ? expf(v - mx) : 0.f;
        float sm = e;
        for (int o = 16; o; o >>= 1) sm += __shfl_xor_sync(0xffffffffu, sm, o);
        if (tid < Tv) score[tid] = e / sm;
    }
    __syncthreads();

    for (int d = tid; d < Dv; d += 128) {
        float s = 0.f;
        #pragma unroll
        for (int t = 0; t < Tv; t++)
            if (validv[t]) s += score[t] * lb[t * Dv + d];
        x[(size_t)bm * Dv + d]  = s;
        xh[(size_t)bm * Dv + d] = __float2half_rn(s);
    }
}

// ======= attention: sums 2 fp16 split-K QKV planes + fp32 bias on load ======
// 16 query rows per block, 128 threads, grid 768. Output fp16.
__global__ void __launch_bounds__(128) attn_kernel(
    const __half* __restrict__ part,    // 2 planes of [1024, 2304] fp16
    const float* __restrict__ qkv_bias, // [2304]
    __half* __restrict__ o)
{
    const int bh = blockIdx.x >> 1;
    const int half_ = blockIdx.x & 1;
    const int b = bh / Hv, h = bh % Hv;
    const int r0 = half_ * 16;

    __shared__ float q[16][68];
    __shared__ float kk[32][68];
    __shared__ float vv[32][68];
    __shared__ float a[16][33];

    const int tid = threadIdx.x;
    const size_t PS = (size_t)NT * 3 * Dv;   // plane stride (halfs)
    const __half* base0 = part + (size_t)(b * Mv) * (3 * Dv) + h * HDv;
    const __half* base1 = base0 + PS;
    const float* bq = qkv_bias + h * HDv;

    #pragma unroll
    for (int rep = 0; rep < 4; rep++) {
        int idx = tid + rep * 128;
        int i = idx >> 5, d2 = idx & 31;
        size_t off = (size_t)(r0 + i) * (3 * Dv) + d2 * 2;
        float2 f0 = __half22float2(*(const __half2*)(base0 + off));
        float2 f1 = __half22float2(*(const __half2*)(base1 + off));
        q[i][d2 * 2]     = f0.x + f1.x + bq[d2 * 2];
        q[i][d2 * 2 + 1] = f0.y + f1.y + bq[d2 * 2 + 1];
    }
    #pragma unroll
    for (int rep = 0; rep < 8; rep++) {
        int idx = tid + rep * 128;
        int i = idx >> 5, d2 = idx & 31;
        size_t off = (size_t)i * (3 * Dv) + d2 * 2;
        float2 k0 = __half22float2(*(const __half2*)(base0 + off + Dv));
        float2 k1 = __half22float2(*(const __half2*)(base1 + off + Dv));
        float2 v0 = __half22float2(*(const __half2*)(base0 + off + 2 * Dv));
        float2 v1 = __half22float2(*(const __half2*)(base1 + off + 2 * Dv));
        kk[i][d2 * 2]     = k0.x + k1.x + bq[Dv + d2 * 2];
        kk[i][d2 * 2 + 1] = k0.y + k1.y + bq[Dv + d2 * 2 + 1];
        vv[i][d2 * 2]     = v0.x + v1.x + bq[2 * Dv + d2 * 2];
        vv[i][d2 * 2 + 1] = v0.y + v1.y + bq[2 * Dv + d2 * 2 + 1];
    }
    __syncthreads();

    #pragma unroll
    for (int rep = 0; rep < 4; rep++) {
        int idx = tid + rep * 128;
        int i = idx >> 5, j = idx & 31;
        float s = 0.f;
        #pragma unroll
        for (int d = 0; d < 64; d += 4) {
            float4 qa = *(const float4*)&q[i][d];
            float4 ka = *(const float4*)&kk[j][d];
            s += qa.x * ka.x + qa.y * ka.y + qa.z * ka.z + qa.w * ka.w;
        }
        a[i][j] = s * 0.125f;
    }
    __syncthreads();

    int warp = tid >> 5, lane = tid & 31;
    #pragma unroll
    for (int r = 0; r < 4; r++) {
        int i = warp * 4 + r;
        float v = a[i][lane];
        float mx = v;
        for (int off = 16; off; off >>= 1) mx = fmaxf(mx, __shfl_xor_sync(0xffffffffu, mx, off));
        float e = expf(v - mx);
        float sm = e;
        for (int off = 16; off; off >>= 1) sm += __shfl_xor_sync(0xffffffffu, sm, off);
        a[i][lane] = e / sm;
    }
    __syncthreads();

    __half* obase = o + (size_t)(b * Mv + r0) * Dv + h * HDv;
    #pragma unroll
    for (int rep = 0; rep < 8; rep++) {
        int idx = tid + rep * 128;
        int i = idx >> 6, d = idx & 63;
        float s = 0.f;
        #pragma unroll
        for (int j = 0; j < 32; j++) s += a[i][j] * vv[j][d];
        obase[(size_t)i * Dv + d] = __float2half_rn(s);
    }
}

// ===== reduce cls1 split-K partials -> padded fp16 hid [1024][128] ==========
__global__ void __launch_bounds__(256) reduce_hid_kernel(
    __half* __restrict__ dst, const float* __restrict__ part, int nPart)
{
    const size_t total = (size_t)NT * 100;
    const size_t stride = (size_t)gridDim.x * blockDim.x;
    for (size_t idx = (size_t)blockIdx.x * blockDim.x + threadIdx.x;
         idx < total; idx += stride) {
        float s = 0.f;
        for (int p = 0; p < nPart; p++) s += part[(size_t)p * total + idx];
        size_t row = idx / 100, col = idx % 100;
        dst[row * 128 + col] = __float2half_rn(s);
    }
}

// ===== reduce split-K partials + bias + residual add + LayerNorm ============
__global__ void __launch_bounds__(256) reduce_addln_kernel(
    float* __restrict__ x, __half* __restrict__ xh,
    const float* __restrict__ part, int nPart,
    const float* __restrict__ bias,
    const float* __restrict__ w, const float* __restrict__ b)
{
    __shared__ float sh[8];
    __shared__ float s_mean, s_inv;
    const int row = blockIdx.x;
    float* xr = x + (size_t)row * Dv;
    __half* xt = xh + (size_t)row * Dv;
    const int tid = threadIdx.x, lane = tid & 31, warp = tid >> 5;
    const size_t planeStride = (size_t)NT * Dv;

    float v[3];
    float sum = 0.f;
    #pragma unroll
    for (int i = 0; i < 3; i++) {
        int idx = tid + 256 * i;
        float d = bias[idx];
        for (int p = 0; p < nPart; p++)
            d += part[(size_t)p * planeStride + (size_t)row * Dv + idx];
        v[i] = xr[idx] + d;
        sum += v[i];
    }
    for (int o = 16; o; o >>= 1) sum += __shfl_xor_sync(0xffffffffu, sum, o);
    if (lane == 0) sh[warp] = sum;
    __syncthreads();
    if (tid == 0) {
        float s = 0.f;
        for (int i = 0; i < 8; i++) s += sh[i];
        s_mean = s * (1.f / (float)Dv);
    }
    __syncthreads();
    float mean = s_mean;

    float sq = 0.f;
    #pragma unroll
    for (int i = 0; i < 3; i++) { float c = v[i] - mean; sq += c * c; }
    for (int o = 16; o; o >>= 1) sq += __shfl_xor_sync(0xffffffffu, sq, o);
    if (lane == 0) sh[warp] = sq;
    __syncthreads();
    if (tid == 0) {
        float s = 0.f;
        for (int i = 0; i < 8; i++) s += sh[i];
        s_inv = rsqrtf(s * (1.f / (float)Dv) + 1e-5f);
    }
    __syncthreads();
    float inv = s_inv;

    #pragma unroll
    for (int i = 0; i < 3; i++) {
        int idx = tid + 256 * i;
        float o = (v[i] - mean) * inv * w[idx] + b[idx];
        xr[idx] = o;
        xt[idx] = __float2half_rn(o);
    }
}

// ======================= launcher ===========================================
extern "C" void kernel_launch(void* const* d_in, const int* in_sizes, int n_in,
                              void* d_out, int out_size)
{
    const float* lhs       = (const float*)d_in[0];
    const float* attn_w    = (const float*)d_in[1];
    const float* attn_b    = (const float*)d_in[2];
    const float* in_proj_w = (const float*)d_in[3];
    const float* in_proj_b = (const float*)d_in[4];
    const float* out_w     = (const float*)d_in[5];
    const float* out_b     = (const float*)d_in[6];
    const float* ln1_w     = (const float*)d_in[7];
    const float* ln1_b     = (const float*)d_in[8];
    const float* lin1_w    = (const float*)d_in[9];
    const float* lin1_b    = (const float*)d_in[10];
    const float* lin2_w    = (const float*)d_in[11];
    const float* lin2_b    = (const float*)d_in[12];
    const float* ln2_w     = (const float*)d_in[13];
    const float* ln2_b     = (const float*)d_in[14];
    const float* cls_w1    = (const float*)d_in[15];
    const float* cls_w2    = (const float*)d_in[16];
    const float* cls_b2    = (const float*)d_in[17];
    const int*   pos       = (const int*)d_in[18];
    const int*   emask     = (const int*)d_in[19];
    float* out = (float*)d_out;

    float  *x, *part;
    __half *xh, *buf1h, *hidh, *wh;
    cudaGetSymbolAddress((void**)&x,     g_x);
    cudaGetSymbolAddress((void**)&xh,    g_xh);
    cudaGetSymbolAddress((void**)&buf1h, g_buf1h);
    cudaGetSymbolAddress((void**)&hidh,  g_hidh);
    cudaGetSymbolAddress((void**)&part,  g_part);
    cudaGetSymbolAddress((void**)&wh,    g_wh);

    cudaFuncSetAttribute(gemm_h, cudaFuncAttributeMaxDynamicSharedMemorySize, GEMMH_SMEM);

    // ---- weight conversion (2 kernels) ----
    cvt_all_kernel<<<2048, 256>>>(in_proj_w, out_w, lin1_w, lin2_w, cls_w1, wh);
    cvt_pad_kernel<<<2048, 256>>>(cls_w2, wh + OFF_C2W);

    pool_kernel<<<NT, 128>>>(lhs, attn_w, attn_b, pos, emask, x, xh);

    for (int l = 0; l < Lv; l++) {
        // QKV: split-K 2 -> 288 blocks, fp16 partial planes consumed by attn
        gemm_h<<<dim3(18, 8, 2), 256, GEMMH_SMEM>>>(
            xh, wh + OFF_IPW + (size_t)l * 3 * Dv * Dv, nullptr,
            part, 3 * Dv, Dv, 384, 2);
        attn_kernel<<<Bv * Hv * 2, 128>>>((const __half*)part,
                                          in_proj_b + (size_t)l * 3 * Dv, buf1h);
        // out-proj: split-K 6 -> 288 blocks, reduce rides LN
        gemm_h<<<dim3(6, 8, 6), 256, GEMMH_SMEM>>>(
            buf1h, wh + OFF_OW + (size_t)l * Dv * Dv, nullptr, part,
            Dv, Dv, 128, 0);
        reduce_addln_kernel<<<NT, 256>>>(x, xh, part, 6, out_b + (size_t)l * Dv,
                                         ln1_w + (size_t)l * Dv, ln1_b + (size_t)l * Dv);
        // lin1: no split, bias+relu fused, fp16 out -> 192 blocks
        gemm_h<<<dim3(24, 8, 1), 256, GEMMH_SMEM>>>(
            xh, wh + OFF_L1W + (size_t)l * DFFv * Dv, lin1_b + (size_t)l * DFFv,
            buf1h, DFFv, Dv, Dv, 3);
        // lin2: K=3072, split-K 6 -> 288 blocks, reduce rides LN
        gemm_h<<<dim3(6, 8, 6), 256, GEMMH_SMEM>>>(
            buf1h, wh + OFF_L2W + (size_t)l * Dv * DFFv, nullptr, part,
            Dv, DFFv, 512, 0);
        reduce_addln_kernel<<<NT, 256>>>(x, xh, part, 6, lin2_b + (size_t)l * Dv,
                                         ln2_w + (size_t)l * Dv, ln2_b + (size_t)l * Dv);
    }

    // classifier stage 1: split-K 4 -> 32 blocks
    gemm_h<<<dim3(1, 8, 4), 256, GEMMH_SMEM>>>(
        xh, wh + OFF_C1W, nullptr, part, 100, Dv, 192, 0);
    reduce_hid_kernel<<<512, 256>>>(hidh, part, 4);
    // classifier stage 2: fp32 out, streaming stores
    gemm_h<<<dim3(782, 8, 1), 256, GEMMH_SMEM>>>(
        hidh, wh + OFF_C2W, cls_b2, out, Ev, 128, 128, 4);
}